// round 3
// baseline (speedup 1.0000x reference)
#include <cuda_runtime.h>
#include <math.h>

#define B_ 2
#define T_ 2048
#define C_ 1024
#define H_ 16
#define D_ 64
#define M_ (B_ * T_)          // 4096 rows
#define SCALE_ 0.125f          // 1/sqrt(64)

// Scratch (allocation-free rule: device globals)
static __device__ float g_Q[(size_t)M_ * C_];
static __device__ float g_K[(size_t)M_ * C_];
static __device__ float g_V[(size_t)M_ * C_];
static __device__ float g_A[(size_t)M_ * C_];

// ---------------------------------------------------------------------------
// C[M,N] = A[M,K] @ W[N,K]^T   (torch Linear convention)
// 128x128 block tile, 256 threads, 8x8 microtile, BK=16, DOUBLE-BUFFERED smem.
// Smem stored K-major transposed: inner loop = 4x LDS.128 + 64 FFMA.
// ---------------------------------------------------------------------------
__device__ __forceinline__ void gemm_nt_body(const float* __restrict__ A,
                                             const float* __restrict__ W,
                                             float* __restrict__ Cout,
                                             int K, int N,
                                             int bm, int bn) {
    __shared__ __align__(16) float As[2][16][128];
    __shared__ __align__(16) float Bs[2][16][128];
    const int tid = threadIdx.x;
    const int tx = tid & 15;         // n micro
    const int ty = tid >> 4;         // m micro
    const float* Ab = A + (size_t)bm * K;
    const float* Wb = W + (size_t)bn * K;

    // Loader mapping: idx = tid + r*256, row = idx>>2 (0..127), kc = (idx&3)*4
    const int lrow0 = tid >> 2;
    const int lkc   = (tid & 3) << 2;

    float acc[8][8];
#pragma unroll
    for (int i = 0; i < 8; i++)
#pragma unroll
        for (int j = 0; j < 8; j++) acc[i][j] = 0.0f;

    // Preload tile 0 into stage 0
    {
#pragma unroll
        for (int r = 0; r < 2; r++) {
            int row = lrow0 + r * 64;
            float4 a = *(const float4*)(Ab + (size_t)row * K + lkc);
            As[0][lkc + 0][row] = a.x; As[0][lkc + 1][row] = a.y;
            As[0][lkc + 2][row] = a.z; As[0][lkc + 3][row] = a.w;
            float4 b = *(const float4*)(Wb + (size_t)row * K + lkc);
            Bs[0][lkc + 0][row] = b.x; Bs[0][lkc + 1][row] = b.y;
            Bs[0][lkc + 2][row] = b.z; Bs[0][lkc + 3][row] = b.w;
        }
    }
    __syncthreads();

    int s = 0;
    for (int k0 = 0; k0 < K; k0 += 16) {
        const bool has_next = (k0 + 16) < K;
        float4 pa[2], pb[2];
        if (has_next) {
#pragma unroll
            for (int r = 0; r < 2; r++) {
                int row = lrow0 + r * 64;
                pa[r] = *(const float4*)(Ab + (size_t)row * K + k0 + 16 + lkc);
                pb[r] = *(const float4*)(Wb + (size_t)row * K + k0 + 16 + lkc);
            }
        }
#pragma unroll
        for (int k = 0; k < 16; k++) {
            float4 a0 = *(const float4*)&As[s][k][(ty << 3) + 0];
            float4 a1 = *(const float4*)&As[s][k][(ty << 3) + 4];
            float4 b0 = *(const float4*)&Bs[s][k][(tx << 3) + 0];
            float4 b1 = *(const float4*)&Bs[s][k][(tx << 3) + 4];
            float av[8] = {a0.x, a0.y, a0.z, a0.w, a1.x, a1.y, a1.z, a1.w};
            float bv[8] = {b0.x, b0.y, b0.z, b0.w, b1.x, b1.y, b1.z, b1.w};
#pragma unroll
            for (int i = 0; i < 8; i++)
#pragma unroll
                for (int j = 0; j < 8; j++) acc[i][j] += av[i] * bv[j];
        }
        if (has_next) {
            const int ns = s ^ 1;
#pragma unroll
            for (int r = 0; r < 2; r++) {
                int row = lrow0 + r * 64;
                As[ns][lkc + 0][row] = pa[r].x; As[ns][lkc + 1][row] = pa[r].y;
                As[ns][lkc + 2][row] = pa[r].z; As[ns][lkc + 3][row] = pa[r].w;
                Bs[ns][lkc + 0][row] = pb[r].x; Bs[ns][lkc + 1][row] = pb[r].y;
                Bs[ns][lkc + 2][row] = pb[r].z; Bs[ns][lkc + 3][row] = pb[r].w;
            }
            __syncthreads();
            s = ns;
        }
    }
#pragma unroll
    for (int i = 0; i < 8; i++) {
        float* crow = Cout + (size_t)(bm + (ty << 3) + i) * N + bn + (tx << 3);
        *(float4*)(crow + 0) = make_float4(acc[i][0], acc[i][1], acc[i][2], acc[i][3]);
        *(float4*)(crow + 4) = make_float4(acc[i][4], acc[i][5], acc[i][6], acc[i][7]);
    }
}

__global__ __launch_bounds__(256) void gemm_nt(const float* __restrict__ A,
                                               const float* __restrict__ W,
                                               float* __restrict__ Cout,
                                               int K, int N) {
    gemm_nt_body(A, W, Cout, K, N, blockIdx.y * 128, blockIdx.x * 128);
}

// Fused Q/K/V projections: grid.z selects weight + destination.
__global__ __launch_bounds__(256) void gemm_qkv(const float* __restrict__ X,
                                                const float* __restrict__ Wq,
                                                const float* __restrict__ Wk,
                                                const float* __restrict__ Wv) {
    const float* W = (blockIdx.z == 0) ? Wq : (blockIdx.z == 1) ? Wk : Wv;
    float* Cout = (blockIdx.z == 0) ? g_Q : (blockIdx.z == 1) ? g_K : g_V;
    gemm_nt_body(X, W, Cout, C_, C_, blockIdx.y * 128, blockIdx.x * 128);
}

// ---------------------------------------------------------------------------
// Flash-attention, fp32. Block = (64 queries) x (one head) x (one batch).
// 256 threads, thread (tx,ty) owns q rows 4ty..4ty+3, keys/dims 4tx..4tx+3.
// Each 16-lane tx-group for a q row sits in ONE warp -> shuffle reductions,
// m/l live in registers. P tile aliases the K tile: exactly 48KB smem.
// ---------------------------------------------------------------------------
__global__ __launch_bounds__(256) void attn_kernel() {
    __shared__ __align__(16) float Qs[64][64];   // [d][q]
    __shared__ __align__(16) float KPs[64][64];  // K: [d][key]  then  P: [q][key]
    __shared__ __align__(16) float Vs[64][64];   // [key][d]

    const int tid = threadIdx.x;
    const int tx = tid & 15;
    const int ty = tid >> 4;
    const int qt = blockIdx.x;          // query tile (0..31)
    const int h  = blockIdx.y;
    const int b  = blockIdx.z;
    const int q0 = qt * 64;

    const float* Qp = g_Q + ((size_t)(b * T_) + q0) * C_ + h * D_;

#pragma unroll
    for (int r = 0; r < 4; r++) {
        int idx = tid + r * 256;
        int row = idx >> 4;            // local q
        int c   = (idx & 15) << 2;     // d
        float4 v = *(const float4*)(Qp + (size_t)row * C_ + c);
        Qs[c + 0][row] = v.x; Qs[c + 1][row] = v.y;
        Qs[c + 2][row] = v.z; Qs[c + 3][row] = v.w;
    }

    float m[4], l[4], o[4][4];
#pragma unroll
    for (int i = 0; i < 4; i++) {
        m[i] = -1e30f;
        l[i] = 0.0f;
#pragma unroll
        for (int j = 0; j < 4; j++) o[i][j] = 0.0f;
    }
    __syncthreads();

    for (int t = 0; t <= qt; t++) {
        const int k0 = t * 64;
        const float* Kp = g_K + ((size_t)(b * T_) + k0) * C_ + h * D_;
        const float* Vp = g_V + ((size_t)(b * T_) + k0) * C_ + h * D_;
#pragma unroll
        for (int r = 0; r < 4; r++) {
            int idx = tid + r * 256;
            int row = idx >> 4;          // local key
            int c   = (idx & 15) << 2;   // d
            float4 kv = *(const float4*)(Kp + (size_t)row * C_ + c);
            KPs[c + 0][row] = kv.x; KPs[c + 1][row] = kv.y;
            KPs[c + 2][row] = kv.z; KPs[c + 3][row] = kv.w;
            float4 vv = *(const float4*)(Vp + (size_t)row * C_ + c);
            *(float4*)&Vs[row][c] = vv;
        }
        __syncthreads();

        // S = Q K^T * scale
        float s[4][4];
#pragma unroll
        for (int i = 0; i < 4; i++)
#pragma unroll
            for (int j = 0; j < 4; j++) s[i][j] = 0.0f;
#pragma unroll 8
        for (int d = 0; d < 64; d++) {
            float4 a4 = *(const float4*)&Qs[d][ty << 2];
            float4 b4 = *(const float4*)&KPs[d][tx << 2];
            float av[4] = {a4.x, a4.y, a4.z, a4.w};
            float bv[4] = {b4.x, b4.y, b4.z, b4.w};
#pragma unroll
            for (int i = 0; i < 4; i++)
#pragma unroll
                for (int j = 0; j < 4; j++) s[i][j] += av[i] * bv[j];
        }
#pragma unroll
        for (int i = 0; i < 4; i++)
#pragma unroll
            for (int j = 0; j < 4; j++) s[i][j] *= SCALE_;
        if (t == qt) {  // diagonal tile: mask key > query
#pragma unroll
            for (int i = 0; i < 4; i++)
#pragma unroll
                for (int j = 0; j < 4; j++)
                    if (((tx << 2) + j) > ((ty << 2) + i)) s[i][j] = -1e30f;
        }
        __syncthreads();  // everyone done reading K tile before P overwrites it

        // online softmax; q-row group = 16 consecutive lanes of one warp
#pragma unroll
        for (int i = 0; i < 4; i++) {
            float mx = fmaxf(fmaxf(s[i][0], s[i][1]), fmaxf(s[i][2], s[i][3]));
#pragma unroll
            for (int off = 1; off < 16; off <<= 1)
                mx = fmaxf(mx, __shfl_xor_sync(0xffffffffu, mx, off));
            float mn = fmaxf(m[i], mx);
            float sc = __expf(m[i] - mn);
            float p[4], ls = 0.0f;
#pragma unroll
            for (int j = 0; j < 4; j++) { p[j] = __expf(s[i][j] - mn); ls += p[j]; }
#pragma unroll
            for (int off = 1; off < 16; off <<= 1)
                ls += __shfl_xor_sync(0xffffffffu, ls, off);
            l[i] = l[i] * sc + ls;
            m[i] = mn;
#pragma unroll
            for (int j = 0; j < 4; j++) o[i][j] *= sc;
#pragma unroll
            for (int j = 0; j < 4; j++) KPs[(ty << 2) + i][(tx << 2) + j] = p[j];
        }
        __syncwarp();   // P rows for our q group are warp-local

        // O += P V
#pragma unroll 8
        for (int kk = 0; kk < 64; kk++) {
            float4 v4 = *(const float4*)&Vs[kk][tx << 2];
            float vv[4] = {v4.x, v4.y, v4.z, v4.w};
            float pv[4];
#pragma unroll
            for (int i = 0; i < 4; i++) pv[i] = KPs[(ty << 2) + i][kk];
#pragma unroll
            for (int i = 0; i < 4; i++)
#pragma unroll
                for (int j = 0; j < 4; j++) o[i][j] += pv[i] * vv[j];
        }
        __syncthreads();  // before next tile load overwrites KPs/Vs
    }

    float* Op = g_A + ((size_t)(b * T_) + q0) * C_ + h * D_;
#pragma unroll
    for (int i = 0; i < 4; i++) {
        float inv = 1.0f / l[i];
        float4 st = make_float4(o[i][0] * inv, o[i][1] * inv,
                                o[i][2] * inv, o[i][3] * inv);
        *(float4*)(Op + (size_t)((ty << 2) + i) * C_ + (tx << 2)) = st;
    }
}

extern "C" void kernel_launch(void* const* d_in, const int* in_sizes, int n_in,
                              void* d_out, int out_size) {
    const float* x  = (const float*)d_in[0];
    const float* Wq = (const float*)d_in[1];
    const float* Wk = (const float*)d_in[2];
    const float* Wv = (const float*)d_in[3];
    const float* Wo = (const float*)d_in[4];

    float* a;
    cudaGetSymbolAddress((void**)&a, g_A);

    dim3 gqkv(C_ / 128, M_ / 128, 3);   // (8, 32, 3)
    gemm_qkv<<<gqkv, 256>>>(x, Wq, Wk, Wv);
    attn_kernel<<<dim3(T_ / 64, H_, B_), 256>>>();
    gemm_nt<<<dim3(C_ / 128, M_ / 128), 256>>>(a, Wo, (float*)d_out, C_, C_);
}

// round 12
// speedup vs baseline: 2.9768x; 2.9768x over previous
#include <cuda_runtime.h>
#include <cstdint>
#include <math.h>

#define B_ 2
#define T_ 2048
#define C_ 1024
#define H_ 16
#define D_ 64
#define M_ (B_ * T_)          // 4096 rows
#define SCALE_ 0.125f          // 1/sqrt(64)

// Scratch (allocation-free rule: device globals)
static __device__ float g_Q[(size_t)M_ * C_];
static __device__ float g_K[(size_t)M_ * C_];
static __device__ float g_V[(size_t)M_ * C_];
static __device__ float g_A[(size_t)M_ * C_];
// tf32-rounded operand copies
static __device__ float g_X[(size_t)M_ * C_];
static __device__ float g_Wq[(size_t)C_ * C_];
static __device__ float g_Wk[(size_t)C_ * C_];
static __device__ float g_Wv[(size_t)C_ * C_];
static __device__ float g_Wo[(size_t)C_ * C_];

// ===========================================================================
// helpers
// ===========================================================================
__device__ __forceinline__ uint32_t smem_u32(const void* p) {
    uint32_t a;
    asm("{ .reg .u64 t; cvta.to.shared.u64 t, %1; cvt.u32.u64 %0, t; }"
        : "=r"(a) : "l"(p));
    return a;
}
__device__ __forceinline__ float tf32r(float x) {
    uint32_t u;
    asm("cvt.rna.tf32.f32 %0, %1;" : "=r"(u) : "f"(x));
    return __uint_as_float(u);
}
__device__ __forceinline__ void cpa16(uint32_t dst, const float* src) {
    asm volatile("cp.async.ca.shared.global [%0], [%1], 16;" :: "r"(dst), "l"(src));
}
#define CP_COMMIT() asm volatile("cp.async.commit_group;" ::: "memory")
#define CP_WAIT(n)  asm volatile("cp.async.wait_group %0;" :: "n"(n) : "memory")

__device__ __forceinline__ void mma8(float* c, const uint32_t* a, const uint32_t* b) {
    asm volatile(
        "mma.sync.aligned.m16n8k8.row.col.f32.tf32.tf32.f32 "
        "{%0,%1,%2,%3}, {%4,%5,%6,%7}, {%8,%9}, {%0,%1,%2,%3};"
        : "+f"(c[0]), "+f"(c[1]), "+f"(c[2]), "+f"(c[3])
        : "r"(a[0]), "r"(a[1]), "r"(a[2]), "r"(a[3]), "r"(b[0]), "r"(b[1]));
}

// ===========================================================================
// Pre-pass: tf32 rounding (exact tf32 operands for cp.async path)
// ===========================================================================
__global__ __launch_bounds__(256) void cvt_tf32_kernel(const float* __restrict__ in,
                                                       float* __restrict__ out) {
    size_t i = ((size_t)blockIdx.x * 256 + threadIdx.x) * 4;
    float4 v = *(const float4*)(in + i);
    v.x = tf32r(v.x); v.y = tf32r(v.y); v.z = tf32r(v.z); v.w = tf32r(v.w);
    *(float4*)(out + i) = v;
}

// All four weight matrices in one launch (gridDim.z selects the pair).
__global__ __launch_bounds__(256) void cvt_tf32_w4(const float* __restrict__ w0,
                                                   const float* __restrict__ w1,
                                                   const float* __restrict__ w2,
                                                   const float* __restrict__ w3) {
    const float* in = (blockIdx.z == 0) ? w0 : (blockIdx.z == 1) ? w1
                    : (blockIdx.z == 2) ? w2 : w3;
    float* out = (blockIdx.z == 0) ? g_Wq : (blockIdx.z == 1) ? g_Wk
               : (blockIdx.z == 2) ? g_Wv : g_Wo;
    size_t i = ((size_t)blockIdx.x * 256 + threadIdx.x) * 4;
    float4 v = *(const float4*)(in + i);
    v.x = tf32r(v.x); v.y = tf32r(v.y); v.z = tf32r(v.z); v.w = tf32r(v.w);
    *(float4*)(out + i) = v;
}

// ===========================================================================
// tf32 mma.sync GEMM:  C[M,N] = A[M,K] @ W[N,K]^T, A/W pre-rounded to tf32.
// CTA 128x128, 8 warps (warp tile 64x32), k-chunk 16, 3-stage cp.async.
// smem rows padded to 20 floats -> conflict-free fragment loads.
// ===========================================================================
#define KC 16
#define STAGES 3
#define TSTR 20                       // floats per smem row
#define TILE_F (128 * TSTR)           // floats per tile per stage
#define SMEM_MMA (STAGES * 2 * TILE_F * 4)   // 61440 bytes
#define NCHUNK (C_ / KC)              // 64

__device__ __forceinline__ void load_chunk(const float* __restrict__ Ab,
                                           const float* __restrict__ Wb,
                                           float* sA, float* sB,
                                           int c, int tid) {
    const int k0 = c * KC;
#pragma unroll
    for (int it = 0; it < 2; it++) {
        int idx = tid + it * 256;        // 0..511
        int row = idx >> 2;              // 0..127
        int f4  = (idx & 3) << 2;        // 0,4,8,12
        cpa16(smem_u32(sA + row * TSTR + f4), Ab + (size_t)row * C_ + k0 + f4);
        cpa16(smem_u32(sB + row * TSTR + f4), Wb + (size_t)row * C_ + k0 + f4);
    }
}

__device__ __forceinline__ void gemm_mma_body(const float* __restrict__ A,
                                              const float* __restrict__ W,
                                              float* __restrict__ Cout,
                                              int bm, int bn) {
    extern __shared__ float smem[];
    float* sA = smem;                       // [STAGES][TILE_F]
    float* sB = smem + STAGES * TILE_F;     // [STAGES][TILE_F]

    const int tid = threadIdx.x;
    const int warp = tid >> 5;
    const int lane = tid & 31;
    const int wm = (warp & 1) * 64;
    const int wn = (warp >> 1) * 32;
    const int lg = lane >> 2;      // group id 0..7
    const int lt = lane & 3;       // thread-in-group

    const float* Ab = A + (size_t)bm * C_;
    const float* Wb = W + (size_t)bn * C_;

    float acc[4][4][4];
#pragma unroll
    for (int i = 0; i < 4; i++)
#pragma unroll
        for (int j = 0; j < 4; j++)
#pragma unroll
            for (int r = 0; r < 4; r++) acc[i][j][r] = 0.0f;

    // prologue: stages 0..STAGES-2
#pragma unroll
    for (int c = 0; c < STAGES - 1; c++) {
        load_chunk(Ab, Wb, sA + c * TILE_F, sB + c * TILE_F, c, tid);
        CP_COMMIT();
    }

    for (int c = 0; c < NCHUNK; c++) {
        CP_WAIT(STAGES - 2);
        __syncthreads();
        const int nc = c + STAGES - 1;
        if (nc < NCHUNK)
            load_chunk(Ab, Wb, sA + (nc % STAGES) * TILE_F,
                       sB + (nc % STAGES) * TILE_F, nc, tid);
        CP_COMMIT();

        const uint32_t* cA = (const uint32_t*)(sA + (c % STAGES) * TILE_F);
        const uint32_t* cB = (const uint32_t*)(sB + (c % STAGES) * TILE_F);
#pragma unroll
        for (int kk = 0; kk < 2; kk++) {
            const int k8 = kk * 8;
            uint32_t af[4][4];
#pragma unroll
            for (int mt = 0; mt < 4; mt++) {
                int r0 = wm + mt * 16 + lg;
                af[mt][0] = cA[(r0)     * TSTR + k8 + lt];
                af[mt][1] = cA[(r0 + 8) * TSTR + k8 + lt];
                af[mt][2] = cA[(r0)     * TSTR + k8 + 4 + lt];
                af[mt][3] = cA[(r0 + 8) * TSTR + k8 + 4 + lt];
            }
            uint32_t bf[4][2];
#pragma unroll
            for (int nt = 0; nt < 4; nt++) {
                int n0 = wn + nt * 8 + lg;
                bf[nt][0] = cB[n0 * TSTR + k8 + lt];
                bf[nt][1] = cB[n0 * TSTR + k8 + 4 + lt];
            }
#pragma unroll
            for (int mt = 0; mt < 4; mt++)
#pragma unroll
                for (int nt = 0; nt < 4; nt++)
                    mma8(acc[mt][nt], af[mt], bf[nt]);
        }
    }

    // epilogue: c0,c1 -> (row, 2lt), (row, 2lt+1); c2,c3 -> row+8
#pragma unroll
    for (int mt = 0; mt < 4; mt++) {
#pragma unroll
        for (int nt = 0; nt < 4; nt++) {
            int row = bm + wm + mt * 16 + lg;
            int col = bn + wn + nt * 8 + lt * 2;
            *(float2*)(Cout + (size_t)row * C_ + col) =
                make_float2(acc[mt][nt][0], acc[mt][nt][1]);
            *(float2*)(Cout + (size_t)(row + 8) * C_ + col) =
                make_float2(acc[mt][nt][2], acc[mt][nt][3]);
        }
    }
}

__global__ __launch_bounds__(256) void gemm_mma_qkv() {
    const float* W = (blockIdx.z == 0) ? g_Wq : (blockIdx.z == 1) ? g_Wk : g_Wv;
    float* Cout = (blockIdx.z == 0) ? g_Q : (blockIdx.z == 1) ? g_K : g_V;
    gemm_mma_body(g_X, W, Cout, blockIdx.y * 128, blockIdx.x * 128);
}
__global__ __launch_bounds__(256) void gemm_mma_wo(float* __restrict__ Cout) {
    gemm_mma_body(g_A, g_Wo, Cout, blockIdx.y * 128, blockIdx.x * 128);
}

// ===========================================================================
// Flash-attention with mma.sync tf32.
// Block = 64 queries x head x batch, 4 warps; warp owns 16 q-rows.
// Smem: Q[64][68], KP[64][68] (K tile then P tile), V[64][72]; all tf32-rounded.
// S = Q K^T via m16n8k8 (8 d-steps x 8 key-tiles); online softmax on the
// accumulator fragment (rows lg/lg+8, shfl_xor 1,2 over the 4-lane group);
// P -> smem (warp-private rows, __syncwarp); O += P V via mma (V as B operand).
// ===========================================================================
#define QP 68
#define VP 72
#define SMEM_ATT ((2 * 64 * QP + 64 * VP) * 4)   // 53248 bytes

__global__ __launch_bounds__(128) void attn_mma() {
    extern __shared__ float as_[];
    float* Qs  = as_;                  // [64][QP]
    float* KPs = as_ + 64 * QP;        // [64][QP]  K tile, then P tile
    float* Vs  = as_ + 2 * 64 * QP;    // [64][VP]
    uint32_t* Qu  = (uint32_t*)Qs;
    uint32_t* KPu = (uint32_t*)KPs;
    uint32_t* Vu  = (uint32_t*)Vs;

    const int tid  = threadIdx.x;
    const int warp = tid >> 5;
    const int lane = tid & 31;
    const int lg = lane >> 2;
    const int lt = lane & 3;
    const int wq0 = warp * 16;          // warp's first q row (local)
    const int qt = blockIdx.x;
    const int h  = blockIdx.y;
    const int b  = blockIdx.z;
    const int q0 = qt * 64;

    // Load Q (tf32-rounded)
    const float* Qp = g_Q + ((size_t)(b * T_) + q0) * C_ + h * D_;
#pragma unroll
    for (int it = 0; it < 8; it++) {
        int idx = tid + it * 128;       // 0..1023
        int row = idx >> 4;
        int c   = (idx & 15) << 2;
        float4 v = *(const float4*)(Qp + (size_t)row * C_ + c);
        float* d = Qs + row * QP + c;
        d[0] = tf32r(v.x); d[1] = tf32r(v.y); d[2] = tf32r(v.z); d[3] = tf32r(v.w);
    }

    float m[2] = {-1e30f, -1e30f};
    float l[2] = {0.0f, 0.0f};
    float o[8][4];
#pragma unroll
    for (int nt = 0; nt < 8; nt++)
#pragma unroll
        for (int r = 0; r < 4; r++) o[nt][r] = 0.0f;

    __syncthreads();

    for (int t = 0; t <= qt; t++) {
        const int k0 = t * 64;
        const float* Kp = g_K + ((size_t)(b * T_) + k0) * C_ + h * D_;
        const float* Vp = g_V + ((size_t)(b * T_) + k0) * C_ + h * D_;
#pragma unroll
        for (int it = 0; it < 8; it++) {
            int idx = tid + it * 128;
            int row = idx >> 4;
            int c   = (idx & 15) << 2;
            float4 kv = *(const float4*)(Kp + (size_t)row * C_ + c);
            float* dk = KPs + row * QP + c;
            dk[0] = tf32r(kv.x); dk[1] = tf32r(kv.y);
            dk[2] = tf32r(kv.z); dk[3] = tf32r(kv.w);
            float4 vv = *(const float4*)(Vp + (size_t)row * C_ + c);
            float* dv = Vs + row * VP + c;
            dv[0] = tf32r(vv.x); dv[1] = tf32r(vv.y);
            dv[2] = tf32r(vv.z); dv[3] = tf32r(vv.w);
        }
        __syncthreads();

        // ---- S = Q K^T (16 q-rows x 64 keys per warp) ----
        float s[8][4];
#pragma unroll
        for (int nt = 0; nt < 8; nt++)
#pragma unroll
            for (int r = 0; r < 4; r++) s[nt][r] = 0.0f;
#pragma unroll
        for (int kt = 0; kt < 8; kt++) {
            const int k8 = kt * 8;
            uint32_t a[4];
            a[0] = Qu[(wq0 + lg)     * QP + k8 + lt];
            a[1] = Qu[(wq0 + lg + 8) * QP + k8 + lt];
            a[2] = Qu[(wq0 + lg)     * QP + k8 + 4 + lt];
            a[3] = Qu[(wq0 + lg + 8) * QP + k8 + 4 + lt];
#pragma unroll
            for (int nt = 0; nt < 8; nt++) {
                uint32_t bf[2];
                bf[0] = KPu[(nt * 8 + lg) * QP + k8 + lt];
                bf[1] = KPu[(nt * 8 + lg) * QP + k8 + 4 + lt];
                mma8(s[nt], a, bf);
            }
        }
#pragma unroll
        for (int nt = 0; nt < 8; nt++)
#pragma unroll
            for (int r = 0; r < 4; r++) s[nt][r] *= SCALE_;

        if (t == qt) {  // diagonal tile: mask key > query
            const int r0 = wq0 + lg, r1 = wq0 + lg + 8;
#pragma unroll
            for (int nt = 0; nt < 8; nt++) {
                int c0 = nt * 8 + 2 * lt, c1 = c0 + 1;
                if (c0 > r0) s[nt][0] = -1e30f;
                if (c1 > r0) s[nt][1] = -1e30f;
                if (c0 > r1) s[nt][2] = -1e30f;
                if (c1 > r1) s[nt][3] = -1e30f;
            }
        }

        // ---- online softmax (rows lg and lg+8) ----
        float mx0 = -1e30f, mx1 = -1e30f;
#pragma unroll
        for (int nt = 0; nt < 8; nt++) {
            mx0 = fmaxf(mx0, fmaxf(s[nt][0], s[nt][1]));
            mx1 = fmaxf(mx1, fmaxf(s[nt][2], s[nt][3]));
        }
        mx0 = fmaxf(mx0, __shfl_xor_sync(0xffffffffu, mx0, 1));
        mx0 = fmaxf(mx0, __shfl_xor_sync(0xffffffffu, mx0, 2));
        mx1 = fmaxf(mx1, __shfl_xor_sync(0xffffffffu, mx1, 1));
        mx1 = fmaxf(mx1, __shfl_xor_sync(0xffffffffu, mx1, 2));
        const float mn0 = fmaxf(m[0], mx0);
        const float mn1 = fmaxf(m[1], mx1);
        const float sc0 = __expf(m[0] - mn0);
        const float sc1 = __expf(m[1] - mn1);
        float ls0 = 0.0f, ls1 = 0.0f;
#pragma unroll
        for (int nt = 0; nt < 8; nt++) {
            s[nt][0] = __expf(s[nt][0] - mn0);
            s[nt][1] = __expf(s[nt][1] - mn0);
            s[nt][2] = __expf(s[nt][2] - mn1);
            s[nt][3] = __expf(s[nt][3] - mn1);
            ls0 += s[nt][0] + s[nt][1];
            ls1 += s[nt][2] + s[nt][3];
        }
        ls0 += __shfl_xor_sync(0xffffffffu, ls0, 1);
        ls0 += __shfl_xor_sync(0xffffffffu, ls0, 2);
        ls1 += __shfl_xor_sync(0xffffffffu, ls1, 1);
        ls1 += __shfl_xor_sync(0xffffffffu, ls1, 2);
        l[0] = l[0] * sc0 + ls0;  m[0] = mn0;
        l[1] = l[1] * sc1 + ls1;  m[1] = mn1;
#pragma unroll
        for (int nt = 0; nt < 8; nt++) {
            o[nt][0] *= sc0; o[nt][1] *= sc0;
            o[nt][2] *= sc1; o[nt][3] *= sc1;
        }

        __syncthreads();  // all warps finished reading K tile before P overwrites

        // ---- write P (tf32-rounded), warp-private rows ----
#pragma unroll
        for (int nt = 0; nt < 8; nt++) {
            int c0 = nt * 8 + 2 * lt;
            float* p0 = KPs + (wq0 + lg) * QP + c0;
            p0[0] = tf32r(s[nt][0]); p0[1] = tf32r(s[nt][1]);
            float* p1 = KPs + (wq0 + lg + 8) * QP + c0;
            p1[0] = tf32r(s[nt][2]); p1[1] = tf32r(s[nt][3]);
        }
        __syncwarp();

        // ---- O += P V ----
#pragma unroll
        for (int kt = 0; kt < 8; kt++) {
            const int k8 = kt * 8;
            uint32_t a[4];
            a[0] = KPu[(wq0 + lg)     * QP + k8 + lt];
            a[1] = KPu[(wq0 + lg + 8) * QP + k8 + lt];
            a[2] = KPu[(wq0 + lg)     * QP + k8 + 4 + lt];
            a[3] = KPu[(wq0 + lg + 8) * QP + k8 + 4 + lt];
#pragma unroll
            for (int nt = 0; nt < 8; nt++) {
                uint32_t bf[2];
                bf[0] = Vu[(k8 + lt)     * VP + nt * 8 + lg];
                bf[1] = Vu[(k8 + 4 + lt) * VP + nt * 8 + lg];
                mma8(o[nt], a, bf);
            }
        }
        __syncthreads();  // before next tile reload of K/V/P smem
    }

    // ---- epilogue: O /= l, rounded tf32 (feeds Wo GEMM) ----
    const float inv0 = 1.0f / l[0];
    const float inv1 = 1.0f / l[1];
    float* Op0 = g_A + ((size_t)(b * T_) + q0 + wq0 + lg) * C_ + h * D_;
    float* Op1 = g_A + ((size_t)(b * T_) + q0 + wq0 + lg + 8) * C_ + h * D_;
#pragma unroll
    for (int nt = 0; nt < 8; nt++) {
        int c0 = nt * 8 + 2 * lt;
        *(float2*)(Op0 + c0) =
            make_float2(tf32r(o[nt][0] * inv0), tf32r(o[nt][1] * inv0));
        *(float2*)(Op1 + c0) =
            make_float2(tf32r(o[nt][2] * inv1), tf32r(o[nt][3] * inv1));
    }
}

extern "C" void kernel_launch(void* const* d_in, const int* in_sizes, int n_in,
                              void* d_out, int out_size) {
    const float* x  = (const float*)d_in[0];
    const float* Wq = (const float*)d_in[1];
    const float* Wk = (const float*)d_in[2];
    const float* Wv = (const float*)d_in[3];
    const float* Wo = (const float*)d_in[4];

    float* xr;
    cudaGetSymbolAddress((void**)&xr, g_X);

    cudaFuncSetAttribute(gemm_mma_qkv, cudaFuncAttributeMaxDynamicSharedMemorySize, SMEM_MMA);
    cudaFuncSetAttribute(gemm_mma_wo,  cudaFuncAttributeMaxDynamicSharedMemorySize, SMEM_MMA);
    cudaFuncSetAttribute(attn_mma,     cudaFuncAttributeMaxDynamicSharedMemorySize, SMEM_ATT);

    // tf32 rounding pre-pass: x, then all four weights in one launch
    cvt_tf32_kernel<<<(M_ * C_) / 1024, 256>>>(x, xr);
    cvt_tf32_w4<<<dim3((C_ * C_) / 1024, 1, 4), 256>>>(Wq, Wk, Wv, Wo);

    dim3 gqkv(C_ / 128, M_ / 128, 3);   // (8, 32, 3)
    gemm_mma_qkv<<<gqkv, 256, SMEM_MMA>>>();
    attn_mma<<<dim3(T_ / 64, H_, B_), 128, SMEM_ATT>>>();
    gemm_mma_wo<<<dim3(C_ / 128, M_ / 128), 256, SMEM_MMA>>>((float*)d_out);
}